// round 4
// baseline (speedup 1.0000x reference)
#include <cuda_runtime.h>
#include <cstdint>
#include <math.h>

// BaseSmear: project 64^3 grid points into 8 camera images, nearest-neighbor
// gather of 32 feature channels + depth + validity + ray direction.
//
//   1) transpose images [I,C,H,W] -> [I,H,W,C] (channels-last) into scratch.
//   2) smear: 4 points/thread, float4 gathers + float4 stores (4x4 register
//      transpose), coords passthrough folded into image-0 blocks.

#define II 8
#define CC 32
#define HH 240
#define WW 320
#define HW (HH*WW)          // 76800
#define NN (64*64*64)       // 262144
#define NN4 (NN/4)          // 65536

__device__ float g_imgT[(size_t)II * HW * CC];   // 78.6 MB channels-last scratch

// ---- Phase 1: [C, HW] -> [HW, C] tile transpose per image ------------------
__global__ __launch_bounds__(256) void transpose_kernel(const float* __restrict__ images) {
    __shared__ float tile[32][33];
    const int tilesPerImg = HW / 32;                 // 2400
    const int i       = blockIdx.x / tilesPerImg;
    const int pixbase = (blockIdx.x % tilesPerImg) * 32;
    const int lane = threadIdx.x & 31;
    const int wy   = threadIdx.x >> 5;               // 0..7

    const float* src = images + (size_t)i * CC * HW + pixbase;
    #pragma unroll
    for (int r = 0; r < 4; r++) {
        const int c = wy + r * 8;
        tile[c][lane] = src[(size_t)c * HW + lane];  // coalesced 128B read per warp
    }
    __syncthreads();
    float* dst = g_imgT + ((size_t)i * HW + pixbase) * CC;
    #pragma unroll
    for (int r = 0; r < 4; r++) {
        const int p = wy + r * 8;
        dst[(size_t)p * CC + lane] = tile[lane][p];  // coalesced 128B write per warp
    }
}

// ---- Phase 2: project + gather + write, 4 points per thread ----------------
__global__ __launch_bounds__(256) void smear_kernel(
    const float* __restrict__ trans,    // [8,3,4]
    const float* __restrict__ Tcw,      // [8,4,4]
    const float* __restrict__ coords,   // [3,64,64,64]
    float* __restrict__ out)            // [8,37,N] then [3,N]
{
    const int bid = blockIdx.x;
    const int i   = bid >> 8;                          // 256 blocks per image
    const int t   = ((bid & 255) << 8) + threadIdx.x;  // 0..65535 (point-quad id)

    const float4* c4 = (const float4*)coords;
    const float4 pxv = c4[t];
    const float4 pyv = c4[NN4 + t];
    const float4 pzv = c4[2 * NN4 + t];

    const float* T = Tcw   + i * 16;   // rows of 4x4 world->cam
    const float* P = trans + i * 12;   // rows of 3x4 projection

    // camera center = -R^T t
    const float ccx = -(T[0] * T[3] + T[4] * T[7] + T[8]  * T[11]);
    const float ccy = -(T[1] * T[3] + T[5] * T[7] + T[9]  * T[11]);
    const float ccz = -(T[2] * T[3] + T[6] * T[7] + T[10] * T[11]);

    float dep[4], vf[4], rdx[4], rdy[4], rdz[4];
    const float4* imgp[4];
    bool vld[4];

    const float px_[4] = {pxv.x, pxv.y, pxv.z, pxv.w};
    const float py_[4] = {pyv.x, pyv.y, pyv.z, pyv.w};
    const float pz_[4] = {pzv.x, pzv.y, pzv.z, pzv.w};

    #pragma unroll
    for (int p = 0; p < 4; p++) {
        const float px = px_[p], py = py_[p], pz = pz_[p];
        const float depth = T[8] * px + T[9] * py + T[10] * pz + T[11];
        const float w  = P[8] * px + P[9] * py + P[10] * pz + P[11];
        const float ws = (fabsf(w) < 1e-8f) ? 1e-8f : w;
        const float u  = (P[0] * px + P[1] * py + P[2] * pz + P[3]) / ws;
        const float v  = (P[4] * px + P[5] * py + P[6] * pz + P[7]) / ws;

        const bool valid = (u >= 0.0f) && (u <= (float)(WW - 1)) &&
                           (v >= 0.0f) && (v <= (float)(HH - 1)) &&
                           (depth > 0.0f);
        const int ui = (int)fminf(fmaxf(rintf(u), 0.0f), (float)(WW - 1));
        const int vi = (int)fminf(fmaxf(rintf(v), 0.0f), (float)(HH - 1));
        const int poff = vi * WW + ui;

        float dx = px - ccx, dy = py - ccy, dz = pz - ccz;
        const float inv = 1.0f / (sqrtf(dx * dx + dy * dy + dz * dz) + 1e-8f);

        dep[p] = depth;
        vf[p]  = valid ? 1.0f : 0.0f;
        vld[p] = valid;
        rdx[p] = dx * inv; rdy[p] = dy * inv; rdz[p] = dz * inv;
        imgp[p] = (const float4*)(g_imgT + ((size_t)i * HW + poff) * CC);
    }

    float4* go4 = (float4*)(out + (size_t)i * 37 * NN) + t;
    const float4 z4 = make_float4(0.f, 0.f, 0.f, 0.f);

    #pragma unroll
    for (int k = 0; k < 8; k++) {
        const float4 f0 = vld[0] ? __ldg(imgp[0] + k) : z4;
        const float4 f1 = vld[1] ? __ldg(imgp[1] + k) : z4;
        const float4 f2 = vld[2] ? __ldg(imgp[2] + k) : z4;
        const float4 f3 = vld[3] ? __ldg(imgp[3] + k) : z4;
        go4[(size_t)(4 * k + 0) * NN4] = make_float4(f0.x, f1.x, f2.x, f3.x);
        go4[(size_t)(4 * k + 1) * NN4] = make_float4(f0.y, f1.y, f2.y, f3.y);
        go4[(size_t)(4 * k + 2) * NN4] = make_float4(f0.z, f1.z, f2.z, f3.z);
        go4[(size_t)(4 * k + 3) * NN4] = make_float4(f0.w, f1.w, f2.w, f3.w);
    }
    go4[(size_t)32 * NN4] = make_float4(dep[0], dep[1], dep[2], dep[3]);
    go4[(size_t)33 * NN4] = make_float4(vf[0],  vf[1],  vf[2],  vf[3]);
    go4[(size_t)34 * NN4] = make_float4(rdx[0], rdx[1], rdx[2], rdx[3]);
    go4[(size_t)35 * NN4] = make_float4(rdy[0], rdy[1], rdy[2], rdy[3]);
    go4[(size_t)36 * NN4] = make_float4(rdz[0], rdz[1], rdz[2], rdz[3]);

    // coordinates passthrough: image-0 blocks write the tail from registers
    if (i == 0) {
        float4* tail4 = (float4*)(out + (size_t)II * 37 * NN);
        tail4[t]           = pxv;
        tail4[NN4 + t]     = pyv;
        tail4[2 * NN4 + t] = pzv;
    }
}

extern "C" void kernel_launch(void* const* d_in, const int* in_sizes, int n_in,
                              void* d_out, int out_size) {
    const float* images = (const float*)d_in[0];
    const float* trans  = (const float*)d_in[1];
    const float* Tcw    = (const float*)d_in[2];
    const float* coords = (const float*)d_in[3];
    float* out = (float*)d_out;

    transpose_kernel<<<II * (HW / 32), 256>>>(images);
    smear_kernel<<<II * (NN / 1024), 256>>>(trans, Tcw, coords, out);
}